// round 5
// baseline (speedup 1.0000x reference)
#include <cuda_runtime.h>
#include <stdint.h>

#define LSEQ   2048
#define DDIM   64
#define KMAX   64
#define NBUCK  2048          // 2^11 buckets per (batch, group)
#define BSHIFT 21            // bucket = code >> 21
#define CAP    16            // Poisson(1) bucket occupancy -> P(overflow) ~ 1e-10
#define NBLK   128           // <= 148 SMs, co-resident => spin barrier safe
#define NTHR   256
#define WPB    (NTHR / 32)   // 8 warps per block
#define NWARP  (NBLK * WPB)  // 1024 warps

// Static device scratch (no allocation allowed). Kernel handles <=4 batches
// per launch; host loops for larger B (bench B = 4 -> single launch).
__device__ int                g_cnt[4 * 2 * NBUCK];
__device__ unsigned long long g_ent[(size_t)4 * 2 * NBUCK * CAP];
__device__ unsigned int       g_bar;    // barrier arrival counter
__device__ unsigned int       g_done;   // completion counter (cleanup elect)

__global__ void __launch_bounds__(NTHR, 1)
fused_kernel(const float* __restrict__ qin, const float* __restrict__ kin,
             float* __restrict__ out, int Bl)
{
    __shared__ uint32_t s_qlo[WPB * 8];
    __shared__ uint32_t s_qhi[WPB * 8];
    __shared__ int s_last;

    const int ntok = Bl * LSEQ;
    const int nqc  = ntok >> 3;                 // chunks of 8 tokens
    const int wib  = threadIdx.x >> 5;
    const int w    = blockIdx.x * WPB + wib;    // global warp id == chunk id
    const int lane = threadIdx.x & 31;

    // ---- Phase B: pack this warp's 8 queries (codes -> smem) and scatter
    //      its 8 keys into the global hash. g_cnt is zero on entry (static
    //      init on first call; re-zeroed by last block on every call). ----
    if (w < nqc) {
        const int t0 = w * 8;
        const int b  = t0 >> 11;                // batch (8 divides LSEQ)
        #pragma unroll
        for (int i = 0; i < 8; i++) {
            const float* qp = qin + (size_t)(t0 + i) * DDIM;
            uint32_t lo = __ballot_sync(0xFFFFFFFFu, qp[lane]      > 0.0f);
            uint32_t hi = __ballot_sync(0xFFFFFFFFu, qp[lane + 32] > 0.0f);
            if (lane == 0) { s_qlo[wib * 8 + i] = lo; s_qhi[wib * 8 + i] = hi; }
        }
        #pragma unroll
        for (int i = 0; i < 8; i++) {
            const float* kp = kin + (size_t)(t0 + i) * DDIM;
            uint32_t lo = __ballot_sync(0xFFFFFFFFu, kp[lane]      > 0.0f);
            uint32_t hi = __ballot_sync(0xFFFFFFFFu, kp[lane + 32] > 0.0f);
            if (lane < 2) {                      // lane0: group0, lane1: group1
                uint32_t code = lane ? hi : lo;  // ballot is warp-uniform
                int idx  = (t0 + i) & (LSEQ - 1);
                int slot = (b * 2 + lane) * NBUCK + (int)(code >> BSHIFT);
                int p = atomicAdd(&g_cnt[slot], 1);
                if (p < CAP)
                    g_ent[(size_t)slot * CAP + p] =
                        ((unsigned long long)code << 32) | (uint32_t)idx;
            }
        }
    }

    // ---- Grid barrier (all 128 blocks resident; release/acquire fenced) ----
    __syncthreads();
    if (threadIdx.x == 0) {
        __threadfence();
        atomicAdd(&g_bar, 1u);
        while (((volatile unsigned int*)&g_bar)[0] < NBLK) __nanosleep(32);
        __threadfence();
    }
    __syncthreads();

    // ---- Phase C: probe + emit ----
    if (w < nqc) {
        const int t0 = w * 8;
        const int b  = t0 >> 11;

        // Parallel probe: lanes 0..7 -> group0 of query (lane), 8..15 -> group1.
        int nm = 0;
        if (lane < 16) {
            int qi  = lane & 7;
            int grp = lane >> 3;
            uint32_t code = grp ? s_qhi[wib * 8 + qi] : s_qlo[wib * 8 + qi];
            int slot = (b * 2 + grp) * NBUCK + (int)(code >> BSHIFT);
            int cnt  = min(__ldcg(&g_cnt[slot]), CAP);
            for (int e = 0; e < cnt; e++) {
                unsigned long long v = __ldcg(&g_ent[(size_t)slot * CAP + e]);
                nm += ((uint32_t)(v >> 32) == code);
            }
        }
        uint32_t mb   = __ballot_sync(0xFFFFFFFFu, nm > 0);
        uint32_t anyb = (mb | (mb >> 8)) & 0xFFu;   // bit i -> query i matched

        // Coalesced -1.0f fill, skipping matched queries (no write races).
        float4* ob = (float4*)(out + (size_t)t0 * KMAX);
        const float4 neg = make_float4(-1.f, -1.f, -1.f, -1.f);
        #pragma unroll
        for (int i = 0; i < 4; i++) {
            int f  = i * 32 + lane;     // float4 index within 128 (16 per query)
            int qi = f >> 4;
            if (!((anyb >> qi) & 1)) ob[f] = neg;
        }

        // Cold slow path: lane qi rebuilds its matched query's full row.
        if (anyb) {
            if (lane < 8 && ((anyb >> lane) & 1)) {
                uint32_t clo = s_qlo[wib * 8 + lane];
                uint32_t chi = s_qhi[wib * 8 + lane];
                int slot0 = (b * 2 + 0) * NBUCK + (int)(clo >> BSHIFT);
                int slot1 = (b * 2 + 1) * NBUCK + (int)(chi >> BSHIFT);
                int c0 = min(__ldcg(&g_cnt[slot0]), CAP);
                int c1 = min(__ldcg(&g_cnt[slot1]), CAP);
                int list[2 * CAP]; int n = 0;
                for (int e = 0; e < c0; e++) {
                    unsigned long long v = __ldcg(&g_ent[(size_t)slot0 * CAP + e]);
                    if ((uint32_t)(v >> 32) == clo) list[n++] = (int)(uint32_t)v;
                }
                for (int e = 0; e < c1; e++) {
                    unsigned long long v = __ldcg(&g_ent[(size_t)slot1 * CAP + e]);
                    if ((uint32_t)(v >> 32) == chi) list[n++] = (int)(uint32_t)v;
                }
                for (int i2 = 1; i2 < n; i2++) {          // ascending sort
                    int key = list[i2], j = i2 - 1;
                    while (j >= 0 && list[j] > key) { list[j + 1] = list[j]; j--; }
                    list[j + 1] = key;
                }
                float* o = out + (size_t)(t0 + lane) * KMAX;
                int pos = 0, prev = -1;
                for (int i2 = 0; i2 < n && pos < KMAX; i2++)
                    if (list[i2] != prev) { o[pos++] = (float)list[i2]; prev = list[i2]; }
                for (; pos < KMAX; pos++) o[pos] = -1.0f;
            }
        }
    }

    // ---- Cleanup: last block to finish re-zeroes counts + barrier state.
    //      All probe values are consumed before the done-increment, so the
    //      reset cannot race any read. ----
    __syncthreads();
    if (threadIdx.x == 0)
        s_last = (atomicAdd(&g_done, 1u) == NBLK - 1);
    __syncthreads();
    if (s_last) {
        int n4 = (Bl * 2 * NBUCK) >> 2;
        for (int i = threadIdx.x; i < n4; i += NTHR)
            ((int4*)g_cnt)[i] = make_int4(0, 0, 0, 0);
        __syncthreads();
        if (threadIdx.x == 0) { g_bar = 0; g_done = 0; __threadfence(); }
    }
}

extern "C" void kernel_launch(void* const* d_in, const int* in_sizes, int n_in,
                              void* d_out, int out_size) {
    const float* q = (const float*)d_in[0];
    const float* k = (const float*)d_in[1];

    int B = out_size / (LSEQ * KMAX);       // out is [B, L, KMAX] float32
    if (B < 1) B = 1;

    for (int b0 = 0; b0 < B; b0 += 4) {     // bench B=4 -> exactly one launch
        int bl = B - b0; if (bl > 4) bl = 4;
        fused_kernel<<<NBLK, NTHR>>>(q + (size_t)b0 * LSEQ * DDIM,
                                     k + (size_t)b0 * LSEQ * DDIM,
                                     (float*)d_out + (size_t)b0 * LSEQ * KMAX,
                                     bl);
    }
}